// round 2
// baseline (speedup 1.0000x reference)
#include <cuda_runtime.h>

// Problem constants (fixed by the reference: B=8, H=16, L=512, D=64)
#define BH   128
#define LSEQ 512
#define DH   64
#define TQ   64     // q rows per block
#define TK   64     // k/v rows per smem tile
#define NTHR 256

#define QS_STRIDE  (DH + 1)     // 65
#define S_STRIDE   (LSEQ + 1)   // 513
#define SMEM_FLOATS (2 * TQ * QS_STRIDE + TQ * S_STRIDE)
#define SMEM_BYTES  (SMEM_FLOATS * sizeof(float))

__global__ __launch_bounds__(NTHR, 1)
void attn_fused_kernel(const float* __restrict__ q,
                       const float* __restrict__ k,
                       const float* __restrict__ v,
                       const float* __restrict__ sel,
                       const int* __restrict__ mask,
                       float* __restrict__ ctx,
                       float* __restrict__ attn)
{
    extern __shared__ float sm[];
    float (*Qs)[QS_STRIDE] = (float (*)[QS_STRIDE])sm;                     // [64][65]
    float (*KVs)[QS_STRIDE] = (float (*)[QS_STRIDE])(sm + TQ * QS_STRIDE); // [64][65]
    float (*S)[S_STRIDE]   = (float (*)[S_STRIDE])(sm + 2 * TQ * QS_STRIDE); // [64][513]

    const int bh  = blockIdx.y;
    const int qt  = blockIdx.x;
    const int tid = threadIdx.x;
    const int tx  = tid & 15;   // 0..15 -> 4 output cols
    const int ty  = tid >> 4;   // 0..15 -> 4 output rows
    const float scale = 0.125f; // 1/sqrt(64)

    // ---- load Q tile [64 x 64] (coalesced float4) ----
    {
        const float4* qv = (const float4*)(q + ((size_t)bh * LSEQ + (size_t)qt * TQ) * DH);
        #pragma unroll
        for (int i = tid; i < TQ * DH / 4; i += NTHR) {
            float4 val = qv[i];
            int e = i * 4;
            int r = e / DH, c = e % DH;
            Qs[r][c + 0] = val.x; Qs[r][c + 1] = val.y;
            Qs[r][c + 2] = val.z; Qs[r][c + 3] = val.w;
        }
    }
    __syncthreads();

    // ---- phase 1: S = Q @ K^T (raw dot products; scale applied in softmax) ----
    for (int kt = 0; kt < LSEQ / TK; ++kt) {
        const float4* kv4 = (const float4*)(k + ((size_t)bh * LSEQ + (size_t)kt * TK) * DH);
        #pragma unroll
        for (int i = tid; i < TK * DH / 4; i += NTHR) {
            float4 val = kv4[i];
            int e = i * 4;
            int r = e / DH, c = e % DH;
            KVs[r][c + 0] = val.x; KVs[r][c + 1] = val.y;
            KVs[r][c + 2] = val.z; KVs[r][c + 3] = val.w;
        }
        __syncthreads();

        float acc[4][4];
        #pragma unroll
        for (int i = 0; i < 4; ++i)
            #pragma unroll
            for (int j = 0; j < 4; ++j) acc[i][j] = 0.f;

        #pragma unroll 8
        for (int kk = 0; kk < DH; ++kk) {
            float a[4], b[4];
            #pragma unroll
            for (int i = 0; i < 4; ++i) a[i] = Qs[4 * ty + i][kk];
            #pragma unroll
            for (int j = 0; j < 4; ++j) b[j] = KVs[4 * tx + j][kk];
            #pragma unroll
            for (int i = 0; i < 4; ++i)
                #pragma unroll
                for (int j = 0; j < 4; ++j)
                    acc[i][j] = fmaf(a[i], b[j], acc[i][j]);
        }

        #pragma unroll
        for (int i = 0; i < 4; ++i)
            #pragma unroll
            for (int j = 0; j < 4; ++j)
                S[4 * ty + i][kt * TK + 4 * tx + j] = acc[i][j];
        __syncthreads();
    }

    // ---- phase 2: softmax per row (warp per row), write attn, keep normalized S ----
    {
        const int warp = tid >> 5, lane = tid & 31;
        const size_t base = (size_t)bh * LSEQ * LSEQ + (size_t)qt * TQ * LSEQ;
        const float* selp = sel + base;
        const int* mp = mask + base;
        float* attnp = attn + base;

        for (int r = warp; r < TQ; r += 8) {
            float vals[16];
            float lmax = -1e30f;
            #pragma unroll
            for (int i = 0; i < 16; ++i) {
                int c = lane + i * 32;
                float s = S[r][c] * scale + selp[(size_t)r * LSEQ + c];
                if (mp[(size_t)r * LSEQ + c] == 0) s = -1e12f;
                vals[i] = s;
                lmax = fmaxf(lmax, s);
            }
            #pragma unroll
            for (int o = 16; o > 0; o >>= 1)
                lmax = fmaxf(lmax, __shfl_xor_sync(0xffffffffu, lmax, o));
            float lsum = 0.f;
            #pragma unroll
            for (int i = 0; i < 16; ++i) {
                vals[i] = __expf(vals[i] - lmax);
                lsum += vals[i];
            }
            #pragma unroll
            for (int o = 16; o > 0; o >>= 1)
                lsum += __shfl_xor_sync(0xffffffffu, lsum, o);
            float inv = 1.0f / lsum;
            #pragma unroll
            for (int i = 0; i < 16; ++i) {
                int c = lane + i * 32;
                float a = vals[i] * inv;
                S[r][c] = a;
                attnp[(size_t)r * LSEQ + c] = a;
            }
        }
    }
    __syncthreads();

    // ---- phase 3: ctx = attn(S) @ V ----
    {
        float acc[4][4];
        #pragma unroll
        for (int i = 0; i < 4; ++i)
            #pragma unroll
            for (int j = 0; j < 4; ++j) acc[i][j] = 0.f;

        for (int kt = 0; kt < LSEQ / TK; ++kt) {
            const float4* vv4 = (const float4*)(v + ((size_t)bh * LSEQ + (size_t)kt * TK) * DH);
            #pragma unroll
            for (int i = tid; i < TK * DH / 4; i += NTHR) {
                float4 val = vv4[i];
                int e = i * 4;
                int r = e / DH, c = e % DH;
                KVs[r][c + 0] = val.x; KVs[r][c + 1] = val.y;
                KVs[r][c + 2] = val.z; KVs[r][c + 3] = val.w;
            }
            __syncthreads();

            #pragma unroll 8
            for (int kk = 0; kk < TK; ++kk) {
                float a[4], b[4];
                #pragma unroll
                for (int i = 0; i < 4; ++i) a[i] = S[4 * ty + i][kt * TK + kk];
                #pragma unroll
                for (int j = 0; j < 4; ++j) b[j] = KVs[kk][4 * tx + j];
                #pragma unroll
                for (int i = 0; i < 4; ++i)
                    #pragma unroll
                    for (int j = 0; j < 4; ++j)
                        acc[i][j] = fmaf(a[i], b[j], acc[i][j]);
            }
            __syncthreads();
        }

        float* cp = ctx + ((size_t)bh * LSEQ + (size_t)qt * TQ) * DH;
        #pragma unroll
        for (int i = 0; i < 4; ++i)
            #pragma unroll
            for (int j = 0; j < 4; ++j)
                cp[(size_t)(4 * ty + i) * DH + (4 * tx + j)] = acc[i][j];
    }
}

extern "C" void kernel_launch(void* const* d_in, const int* in_sizes, int n_in,
                              void* d_out, int out_size)
{
    (void)in_sizes; (void)n_in; (void)out_size;
    const float* q = (const float*)d_in[0];
    const float* k = (const float*)d_in[1];
    const float* v = (const float*)d_in[2];
    const float* sel = (const float*)d_in[3];
    const int* mask = (const int*)d_in[4];

    float* ctx  = (float*)d_out;                          // [128,512,64]
    float* attn = ctx + (size_t)BH * LSEQ * DH;           // [128,512,512]

    cudaFuncSetAttribute(attn_fused_kernel,
                         cudaFuncAttributeMaxDynamicSharedMemorySize, (int)SMEM_BYTES);

    dim3 grid(LSEQ / TQ, BH);   // (8, 128) = 1024 blocks
    attn_fused_kernel<<<grid, NTHR, SMEM_BYTES>>>(q, k, v, sel, mask, ctx, attn);
}

// round 3
// speedup vs baseline: 1.0017x; 1.0017x over previous
#include <cuda_runtime.h>

// Problem constants (fixed by the reference: B=8, H=16, L=512, D=64)
#define BH   128
#define LSEQ 512
#define DH   64
#define TQ   64     // q rows per block
#define TK   64     // k/v rows per smem tile
#define NTHR 256

#define QS_STRIDE  (DH + 1)     // 65
#define S_STRIDE   (LSEQ + 1)   // 513
#define SMEM_FLOATS (2 * TQ * QS_STRIDE + TQ * S_STRIDE)
#define SMEM_BYTES  (SMEM_FLOATS * sizeof(float))

__global__ __launch_bounds__(NTHR, 1)
void attn_fused_kernel(const float* __restrict__ q,
                       const float* __restrict__ k,
                       const float* __restrict__ v,
                       const float* __restrict__ sel,
                       const int* __restrict__ mask,
                       float* __restrict__ ctx,
                       float* __restrict__ attn)
{
    extern __shared__ float sm[];
    float (*Qs)[QS_STRIDE] = (float (*)[QS_STRIDE])sm;                     // [64][65]
    float (*KVs)[QS_STRIDE] = (float (*)[QS_STRIDE])(sm + TQ * QS_STRIDE); // [64][65]
    float (*S)[S_STRIDE]   = (float (*)[S_STRIDE])(sm + 2 * TQ * QS_STRIDE); // [64][513]

    const int bh  = blockIdx.y;
    const int qt  = blockIdx.x;
    const int tid = threadIdx.x;
    const int tx  = tid & 15;   // 0..15 -> 4 output cols
    const int ty  = tid >> 4;   // 0..15 -> 4 output rows
    const float scale = 0.125f; // 1/sqrt(64)

    // ---- load Q tile [64 x 64] (coalesced float4) ----
    {
        const float4* qv = (const float4*)(q + ((size_t)bh * LSEQ + (size_t)qt * TQ) * DH);
        #pragma unroll
        for (int i = tid; i < TQ * DH / 4; i += NTHR) {
            float4 val = qv[i];
            int e = i * 4;
            int r = e / DH, c = e % DH;
            Qs[r][c + 0] = val.x; Qs[r][c + 1] = val.y;
            Qs[r][c + 2] = val.z; Qs[r][c + 3] = val.w;
        }
    }
    __syncthreads();

    // ---- phase 1: S = Q @ K^T (raw dot products; scale applied in softmax) ----
    for (int kt = 0; kt < LSEQ / TK; ++kt) {
        const float4* kv4 = (const float4*)(k + ((size_t)bh * LSEQ + (size_t)kt * TK) * DH);
        #pragma unroll
        for (int i = tid; i < TK * DH / 4; i += NTHR) {
            float4 val = kv4[i];
            int e = i * 4;
            int r = e / DH, c = e % DH;
            KVs[r][c + 0] = val.x; KVs[r][c + 1] = val.y;
            KVs[r][c + 2] = val.z; KVs[r][c + 3] = val.w;
        }
        __syncthreads();

        float acc[4][4];
        #pragma unroll
        for (int i = 0; i < 4; ++i)
            #pragma unroll
            for (int j = 0; j < 4; ++j) acc[i][j] = 0.f;

        #pragma unroll 8
        for (int kk = 0; kk < DH; ++kk) {
            float a[4], b[4];
            #pragma unroll
            for (int i = 0; i < 4; ++i) a[i] = Qs[4 * ty + i][kk];
            #pragma unroll
            for (int j = 0; j < 4; ++j) b[j] = KVs[4 * tx + j][kk];
            #pragma unroll
            for (int i = 0; i < 4; ++i)
                #pragma unroll
                for (int j = 0; j < 4; ++j)
                    acc[i][j] = fmaf(a[i], b[j], acc[i][j]);
        }

        #pragma unroll
        for (int i = 0; i < 4; ++i)
            #pragma unroll
            for (int j = 0; j < 4; ++j)
                S[4 * ty + i][kt * TK + 4 * tx + j] = acc[i][j];
        __syncthreads();
    }

    // ---- phase 2: softmax per row (warp per row), write attn, keep normalized S ----
    {
        const int warp = tid >> 5, lane = tid & 31;
        const size_t base = (size_t)bh * LSEQ * LSEQ + (size_t)qt * TQ * LSEQ;
        const float* selp = sel + base;
        const int* mp = mask + base;
        float* attnp = attn + base;

        for (int r = warp; r < TQ; r += 8) {
            float vals[16];
            float lmax = -1e30f;
            #pragma unroll
            for (int i = 0; i < 16; ++i) {
                int c = lane + i * 32;
                float s = S[r][c] * scale + selp[(size_t)r * LSEQ + c];
                if (mp[(size_t)r * LSEQ + c] == 0) s = -1e12f;
                vals[i] = s;
                lmax = fmaxf(lmax, s);
            }
            #pragma unroll
            for (int o = 16; o > 0; o >>= 1)
                lmax = fmaxf(lmax, __shfl_xor_sync(0xffffffffu, lmax, o));
            float lsum = 0.f;
            #pragma unroll
            for (int i = 0; i < 16; ++i) {
                vals[i] = __expf(vals[i] - lmax);
                lsum += vals[i];
            }
            #pragma unroll
            for (int o = 16; o > 0; o >>= 1)
                lsum += __shfl_xor_sync(0xffffffffu, lsum, o);
            float inv = 1.0f / lsum;
            #pragma unroll
            for (int i = 0; i < 16; ++i) {
                int c = lane + i * 32;
                float a = vals[i] * inv;
                S[r][c] = a;
                attnp[(size_t)r * LSEQ + c] = a;
            }
        }
    }
    __syncthreads();

    // ---- phase 3: ctx = attn(S) @ V ----
    {
        float acc[4][4];
        #pragma unroll
        for (int i = 0; i < 4; ++i)
            #pragma unroll
            for (int j = 0; j < 4; ++j) acc[i][j] = 0.f;

        for (int kt = 0; kt < LSEQ / TK; ++kt) {
            const float4* vv4 = (const float4*)(v + ((size_t)bh * LSEQ + (size_t)kt * TK) * DH);
            #pragma unroll
            for (int i = tid; i < TK * DH / 4; i += NTHR) {
                float4 val = vv4[i];
                int e = i * 4;
                int r = e / DH, c = e % DH;
                KVs[r][c + 0] = val.x; KVs[r][c + 1] = val.y;
                KVs[r][c + 2] = val.z; KVs[r][c + 3] = val.w;
            }
            __syncthreads();

            #pragma unroll 8
            for (int kk = 0; kk < TK; ++kk) {
                float a[4], b[4];
                #pragma unroll
                for (int i = 0; i < 4; ++i) a[i] = S[4 * ty + i][kt * TK + kk];
                #pragma unroll
                for (int j = 0; j < 4; ++j) b[j] = KVs[kk][4 * tx + j];
                #pragma unroll
                for (int i = 0; i < 4; ++i)
                    #pragma unroll
                    for (int j = 0; j < 4; ++j)
                        acc[i][j] = fmaf(a[i], b[j], acc[i][j]);
            }
            __syncthreads();
        }

        float* cp = ctx + ((size_t)bh * LSEQ + (size_t)qt * TQ) * DH;
        #pragma unroll
        for (int i = 0; i < 4; ++i)
            #pragma unroll
            for (int j = 0; j < 4; ++j)
                cp[(size_t)(4 * ty + i) * DH + (4 * tx + j)] = acc[i][j];
    }
}

extern "C" void kernel_launch(void* const* d_in, const int* in_sizes, int n_in,
                              void* d_out, int out_size)
{
    (void)in_sizes; (void)n_in; (void)out_size;
    const float* q = (const float*)d_in[0];
    const float* k = (const float*)d_in[1];
    const float* v = (const float*)d_in[2];
    const float* sel = (const float*)d_in[3];
    const int* mask = (const int*)d_in[4];

    float* ctx  = (float*)d_out;                          // [128,512,64]
    float* attn = ctx + (size_t)BH * LSEQ * DH;           // [128,512,512]

    cudaFuncSetAttribute(attn_fused_kernel,
                         cudaFuncAttributeMaxDynamicSharedMemorySize, (int)SMEM_BYTES);

    dim3 grid(LSEQ / TQ, BH);   // (8, 128) = 1024 blocks
    attn_fused_kernel<<<grid, NTHR, SMEM_BYTES>>>(q, k, v, sel, mask, ctx, attn);
}

// round 4
// speedup vs baseline: 1.7236x; 1.7207x over previous
#include <cuda_runtime.h>
#include <cstdint>

// Problem constants (fixed by the reference: B=8, H=16, L=512, D=64)
#define BH   128
#define LSEQ 512
#define DH   64
#define TQ   64     // q rows per block
#define TK   64     // k/v rows per smem tile
#define NTHR 256

#define QS_STRIDE  68           // %32==4 -> conflict-free fragment loads
#define S_STRIDE   516          // %32==4
#define SMEM_FLOATS (2 * TQ * QS_STRIDE + TQ * S_STRIDE)
#define SMEM_BYTES  (SMEM_FLOATS * sizeof(float))

__device__ __forceinline__ uint32_t f2tf(float x) {
    uint32_t r;
    asm("cvt.rna.tf32.f32 %0, %1;" : "=r"(r) : "f"(x));
    return r;
}

__device__ __forceinline__ void mma_tf32(float d[4], const uint32_t a[4], const uint32_t b[2]) {
    asm volatile(
        "mma.sync.aligned.m16n8k8.row.col.f32.tf32.tf32.f32 "
        "{%0,%1,%2,%3}, {%4,%5,%6,%7}, {%8,%9}, {%0,%1,%2,%3};\n"
        : "+f"(d[0]), "+f"(d[1]), "+f"(d[2]), "+f"(d[3])
        : "r"(a[0]), "r"(a[1]), "r"(a[2]), "r"(a[3]), "r"(b[0]), "r"(b[1]));
}

__global__ __launch_bounds__(NTHR, 1)
void attn_fused_kernel(const float* __restrict__ q,
                       const float* __restrict__ k,
                       const float* __restrict__ v,
                       const float* __restrict__ sel,
                       const int* __restrict__ mask,
                       float* __restrict__ ctx,
                       float* __restrict__ attn)
{
    extern __shared__ float sm[];
    float (*Qs)[QS_STRIDE] = (float (*)[QS_STRIDE])sm;                       // [64][68]
    float (*KVs)[QS_STRIDE] = (float (*)[QS_STRIDE])(sm + TQ * QS_STRIDE);   // [64][68]
    float (*S)[S_STRIDE]   = (float (*)[S_STRIDE])(sm + 2 * TQ * QS_STRIDE); // [64][516]

    const int bh  = blockIdx.y;
    const int qt  = blockIdx.x;
    const int tid = threadIdx.x;
    const int warp = tid >> 5, lane = tid & 31;
    const int wm = warp >> 1;          // 4 warps along M: rows wm*16..+15
    const int wn = warp & 1;           // 2 warps along N: cols wn*32..+31
    const int g  = lane >> 2;          // fragment group 0..7
    const int t  = lane & 3;           // fragment thread-in-group 0..3
    const float scale = 0.125f;        // 1/sqrt(64)

    // ---- load Q tile [64 x 64] (coalesced float4) ----
    {
        const float4* qv = (const float4*)(q + ((size_t)bh * LSEQ + (size_t)qt * TQ) * DH);
        #pragma unroll
        for (int i = tid; i < TQ * DH / 4; i += NTHR) {
            float4 val = qv[i];
            int e = i * 4;
            int r = e / DH, c = e % DH;
            Qs[r][c + 0] = val.x; Qs[r][c + 1] = val.y;
            Qs[r][c + 2] = val.z; Qs[r][c + 3] = val.w;
        }
    }
    __syncthreads();

    // ---- phase 1: S = Q @ K^T via tf32 mma ----
    for (int kt = 0; kt < LSEQ / TK; ++kt) {
        const float4* kv4 = (const float4*)(k + ((size_t)bh * LSEQ + (size_t)kt * TK) * DH);
        #pragma unroll
        for (int i = tid; i < TK * DH / 4; i += NTHR) {
            float4 val = kv4[i];
            int e = i * 4;
            int r = e / DH, c = e % DH;
            KVs[r][c + 0] = val.x; KVs[r][c + 1] = val.y;
            KVs[r][c + 2] = val.z; KVs[r][c + 3] = val.w;
        }
        __syncthreads();

        float acc[4][4];
        #pragma unroll
        for (int nt = 0; nt < 4; ++nt)
            #pragma unroll
            for (int j = 0; j < 4; ++j) acc[nt][j] = 0.f;

        #pragma unroll
        for (int ks = 0; ks < DH / 8; ++ks) {
            const int k0 = ks * 8;
            uint32_t a[4];
            a[0] = f2tf(Qs[wm * 16 + g    ][k0 + t    ]);
            a[1] = f2tf(Qs[wm * 16 + g + 8][k0 + t    ]);
            a[2] = f2tf(Qs[wm * 16 + g    ][k0 + t + 4]);
            a[3] = f2tf(Qs[wm * 16 + g + 8][k0 + t + 4]);
            #pragma unroll
            for (int nt = 0; nt < 4; ++nt) {
                const int n0 = wn * 32 + nt * 8;
                uint32_t b[2];
                b[0] = f2tf(KVs[n0 + g][k0 + t    ]);
                b[1] = f2tf(KVs[n0 + g][k0 + t + 4]);
                mma_tf32(acc[nt], a, b);
            }
        }

        #pragma unroll
        for (int nt = 0; nt < 4; ++nt) {
            const int n0 = kt * TK + wn * 32 + nt * 8 + 2 * t;
            S[wm * 16 + g    ][n0    ] = acc[nt][0];
            S[wm * 16 + g    ][n0 + 1] = acc[nt][1];
            S[wm * 16 + g + 8][n0    ] = acc[nt][2];
            S[wm * 16 + g + 8][n0 + 1] = acc[nt][3];
        }
        __syncthreads();
    }

    // ---- phase 2: softmax per row (warp per row), vectorized global I/O ----
    {
        const size_t base = (size_t)bh * LSEQ * LSEQ + (size_t)qt * TQ * LSEQ;
        const float* selp = sel + base;
        const int* mp = mask + base;
        float* attnp = attn + base;

        for (int r = warp; r < TQ; r += 8) {
            float vals[16];
            float lmax = -1e30f;
            #pragma unroll
            for (int i = 0; i < 4; ++i) {
                const int c = i * 128 + lane * 4;
                float4 sv = *(const float4*)&S[r][c];
                float4 se = *(const float4*)&selp[(size_t)r * LSEQ + c];
                int4  mv = *(const int4*)&mp[(size_t)r * LSEQ + c];
                float x0 = sv.x * scale + se.x; if (mv.x == 0) x0 = -1e12f;
                float x1 = sv.y * scale + se.y; if (mv.y == 0) x1 = -1e12f;
                float x2 = sv.z * scale + se.z; if (mv.z == 0) x2 = -1e12f;
                float x3 = sv.w * scale + se.w; if (mv.w == 0) x3 = -1e12f;
                vals[4 * i + 0] = x0; vals[4 * i + 1] = x1;
                vals[4 * i + 2] = x2; vals[4 * i + 3] = x3;
                lmax = fmaxf(lmax, fmaxf(fmaxf(x0, x1), fmaxf(x2, x3)));
            }
            #pragma unroll
            for (int o = 16; o > 0; o >>= 1)
                lmax = fmaxf(lmax, __shfl_xor_sync(0xffffffffu, lmax, o));
            float lsum = 0.f;
            #pragma unroll
            for (int i = 0; i < 16; ++i) {
                vals[i] = __expf(vals[i] - lmax);
                lsum += vals[i];
            }
            #pragma unroll
            for (int o = 16; o > 0; o >>= 1)
                lsum += __shfl_xor_sync(0xffffffffu, lsum, o);
            const float inv = 1.0f / lsum;
            #pragma unroll
            for (int i = 0; i < 4; ++i) {
                const int c = i * 128 + lane * 4;
                float4 a4;
                a4.x = vals[4 * i + 0] * inv;
                a4.y = vals[4 * i + 1] * inv;
                a4.z = vals[4 * i + 2] * inv;
                a4.w = vals[4 * i + 3] * inv;
                *(float4*)&S[r][c] = a4;
                *(float4*)&attnp[(size_t)r * LSEQ + c] = a4;
            }
        }
    }
    __syncthreads();

    // ---- phase 3: ctx = P(S) @ V via tf32 mma ----
    {
        float acc[4][4];
        #pragma unroll
        for (int nt = 0; nt < 4; ++nt)
            #pragma unroll
            for (int j = 0; j < 4; ++j) acc[nt][j] = 0.f;

        for (int kt = 0; kt < LSEQ / TK; ++kt) {
            const float4* vv4 = (const float4*)(v + ((size_t)bh * LSEQ + (size_t)kt * TK) * DH);
            #pragma unroll
            for (int i = tid; i < TK * DH / 4; i += NTHR) {
                float4 val = vv4[i];
                int e = i * 4;
                int r = e / DH, c = e % DH;
                KVs[r][c + 0] = val.x; KVs[r][c + 1] = val.y;
                KVs[r][c + 2] = val.z; KVs[r][c + 3] = val.w;
            }
            __syncthreads();

            #pragma unroll
            for (int ks = 0; ks < TK / 8; ++ks) {
                const int sk = kt * TK + ks * 8;   // S column (k index)
                const int vk = ks * 8;             // V smem row
                uint32_t a[4];
                a[0] = f2tf(S[wm * 16 + g    ][sk + t    ]);
                a[1] = f2tf(S[wm * 16 + g + 8][sk + t    ]);
                a[2] = f2tf(S[wm * 16 + g    ][sk + t + 4]);
                a[3] = f2tf(S[wm * 16 + g + 8][sk + t + 4]);
                #pragma unroll
                for (int nt = 0; nt < 4; ++nt) {
                    const int n0 = wn * 32 + nt * 8;
                    uint32_t b[2];
                    b[0] = f2tf(KVs[vk + t    ][n0 + g]);
                    b[1] = f2tf(KVs[vk + t + 4][n0 + g]);
                    mma_tf32(acc[nt], a, b);
                }
            }
            __syncthreads();
        }

        float* cp = ctx + ((size_t)bh * LSEQ + (size_t)qt * TQ) * DH;
        #pragma unroll
        for (int nt = 0; nt < 4; ++nt) {
            const int n0 = wn * 32 + nt * 8 + 2 * t;
            float2 lo = make_float2(acc[nt][0], acc[nt][1]);
            float2 hi = make_float2(acc[nt][2], acc[nt][3]);
            *(float2*)&cp[(size_t)(wm * 16 + g    ) * DH + n0] = lo;
            *(float2*)&cp[(size_t)(wm * 16 + g + 8) * DH + n0] = hi;
        }
    }
}

extern "C" void kernel_launch(void* const* d_in, const int* in_sizes, int n_in,
                              void* d_out, int out_size)
{
    (void)in_sizes; (void)n_in; (void)out_size;
    const float* q = (const float*)d_in[0];
    const float* k = (const float*)d_in[1];
    const float* v = (const float*)d_in[2];
    const float* sel = (const float*)d_in[3];
    const int* mask = (const int*)d_in[4];

    float* ctx  = (float*)d_out;                          // [128,512,64]
    float* attn = ctx + (size_t)BH * LSEQ * DH;           // [128,512,512]

    cudaFuncSetAttribute(attn_fused_kernel,
                         cudaFuncAttributeMaxDynamicSharedMemorySize, (int)SMEM_BYTES);

    dim3 grid(LSEQ / TQ, BH);   // (8, 128) = 1024 blocks
    attn_fused_kernel<<<grid, NTHR, SMEM_BYTES>>>(q, k, v, sel, mask, ctx, attn);
}

// round 5
// speedup vs baseline: 2.3478x; 1.3621x over previous
#include <cuda_runtime.h>
#include <cstdint>

// Problem constants (fixed by the reference: B=8, H=16, L=512, D=64)
#define BH   128
#define LSEQ 512
#define DH   64
#define TQ   64     // q rows per block
#define TK   64     // k/v rows per smem tile
#define NTHR 512

#define QS_STRIDE  68           // %32==4 -> conflict-free fragment loads
#define S_STRIDE   516          // %32==4
#define SMEM_FLOATS (TQ * QS_STRIDE + 2 * TK * QS_STRIDE + TQ * S_STRIDE)
#define SMEM_BYTES  (SMEM_FLOATS * sizeof(float))

__device__ __forceinline__ uint32_t f2tf(float x) {
    uint32_t r;
    asm("cvt.rna.tf32.f32 %0, %1;" : "=r"(r) : "f"(x));
    return r;
}

__device__ __forceinline__ void mma_tf32(float d[4], const uint32_t a[4], const uint32_t b[2]) {
    asm volatile(
        "mma.sync.aligned.m16n8k8.row.col.f32.tf32.tf32.f32 "
        "{%0,%1,%2,%3}, {%4,%5,%6,%7}, {%8,%9}, {%0,%1,%2,%3};\n"
        : "+f"(d[0]), "+f"(d[1]), "+f"(d[2]), "+f"(d[3])
        : "r"(a[0]), "r"(a[1]), "r"(a[2]), "r"(a[3]), "r"(b[0]), "r"(b[1]));
}

__device__ __forceinline__ void cp_async16(void* smem_ptr, const void* gptr) {
    uint32_t s = (uint32_t)__cvta_generic_to_shared(smem_ptr);
    asm volatile("cp.async.cg.shared.global [%0], [%1], 16;" :: "r"(s), "l"(gptr));
}
#define CP_COMMIT()  asm volatile("cp.async.commit_group;")
#define CP_WAIT0()   asm volatile("cp.async.wait_group 0;")

__global__ __launch_bounds__(NTHR, 1)
void attn_fused_kernel(const float* __restrict__ q,
                       const float* __restrict__ k,
                       const float* __restrict__ v,
                       const float* __restrict__ sel,
                       const int* __restrict__ mask,
                       float* __restrict__ ctx,
                       float* __restrict__ attn)
{
    extern __shared__ float sm[];
    float (*Qs)[QS_STRIDE]    = (float (*)[QS_STRIDE])sm;                         // [64][68]
    float (*KV)[TK][QS_STRIDE]= (float (*)[TK][QS_STRIDE])(sm + TQ * QS_STRIDE);  // [2][64][68]
    float (*S)[S_STRIDE]      = (float (*)[S_STRIDE])(sm + TQ * QS_STRIDE + 2 * TK * QS_STRIDE); // [64][516]

    const int bh  = blockIdx.y;
    const int qt  = blockIdx.x;
    const int tid = threadIdx.x;
    const int warp = tid >> 5, lane = tid & 31;
    const int wm = warp & 3;           // 4 warps along M: rows wm*16..+15
    const int wn = warp >> 2;          // 4 warps along N: 16 cols each
    const int g  = lane >> 2;          // fragment group 0..7
    const int t  = lane & 3;           // fragment thread-in-group 0..3
    const float scale = 0.125f;        // 1/sqrt(64)

    const float* qg = q + ((size_t)bh * LSEQ + (size_t)qt * TQ) * DH;
    const float* kg = k + (size_t)bh * LSEQ * DH;
    const float* vg = v + (size_t)bh * LSEQ * DH;

    // ---- prologue: async load Q tile + K tile 0 ----
    #pragma unroll
    for (int i = tid; i < TQ * DH / 4; i += NTHR) {
        int e = i * 4, r = e >> 6, c = e & 63;
        cp_async16(&Qs[r][c], qg + e);
        cp_async16(&KV[0][r][c], kg + e);
    }
    CP_COMMIT();
    CP_WAIT0();
    __syncthreads();

    // ---- hoist Q tf32 fragments (invariant across K tiles) ----
    uint32_t qa[DH / 8][4];
    #pragma unroll
    for (int ks = 0; ks < DH / 8; ++ks) {
        const int k0 = ks * 8;
        qa[ks][0] = f2tf(Qs[wm * 16 + g    ][k0 + t    ]);
        qa[ks][1] = f2tf(Qs[wm * 16 + g + 8][k0 + t    ]);
        qa[ks][2] = f2tf(Qs[wm * 16 + g    ][k0 + t + 4]);
        qa[ks][3] = f2tf(Qs[wm * 16 + g + 8][k0 + t + 4]);
    }

    // ---- phase 1: S = Q @ K^T via tf32 mma, double-buffered K tiles ----
    for (int kt = 0; kt < LSEQ / TK; ++kt) {
        if (kt > 0) {
            CP_WAIT0();
            __syncthreads();
        }
        if (kt + 1 < LSEQ / TK) {
            const float* kn = kg + (size_t)(kt + 1) * TK * DH;
            #pragma unroll
            for (int i = tid; i < TK * DH / 4; i += NTHR) {
                int e = i * 4, r = e >> 6, c = e & 63;
                cp_async16(&KV[(kt + 1) & 1][r][c], kn + e);
            }
            CP_COMMIT();
        }

        float (*Ks)[QS_STRIDE] = KV[kt & 1];
        float acc[2][4];
        #pragma unroll
        for (int nt = 0; nt < 2; ++nt)
            #pragma unroll
            for (int j = 0; j < 4; ++j) acc[nt][j] = 0.f;

        #pragma unroll
        for (int ks = 0; ks < DH / 8; ++ks) {
            const int k0 = ks * 8;
            #pragma unroll
            for (int nt = 0; nt < 2; ++nt) {
                const int n0 = wn * 16 + nt * 8;
                uint32_t b[2];
                b[0] = f2tf(Ks[n0 + g][k0 + t    ]);
                b[1] = f2tf(Ks[n0 + g][k0 + t + 4]);
                mma_tf32(acc[nt], qa[ks], b);
            }
        }

        #pragma unroll
        for (int nt = 0; nt < 2; ++nt) {
            const int n0 = kt * TK + wn * 16 + nt * 8 + 2 * t;
            S[wm * 16 + g    ][n0    ] = acc[nt][0];
            S[wm * 16 + g    ][n0 + 1] = acc[nt][1];
            S[wm * 16 + g + 8][n0    ] = acc[nt][2];
            S[wm * 16 + g + 8][n0 + 1] = acc[nt][3];
        }
    }

    // prefetch V tile 0 into buf 0 (overlaps softmax); buf0 last read at kt=6,
    // whose consumers all passed the kt=7 barrier above.
    #pragma unroll
    for (int i = tid; i < TK * DH / 4; i += NTHR) {
        int e = i * 4, r = e >> 6, c = e & 63;
        cp_async16(&KV[0][r][c], vg + e);
    }
    CP_COMMIT();
    __syncthreads();   // S complete for softmax

    // ---- phase 2: softmax, 4 rows per warp, vectorized global I/O ----
    {
        const size_t base = (size_t)bh * LSEQ * LSEQ + (size_t)qt * TQ * LSEQ;
        const float* selp = sel + base;
        const int* mp = mask + base;
        float* attnp = attn + base;

        #pragma unroll
        for (int rr = 0; rr < 4; ++rr) {
            const int r = warp * 4 + rr;
            float vals[16];
            float lmax = -1e30f;
            #pragma unroll
            for (int i = 0; i < 4; ++i) {
                const int c = i * 128 + lane * 4;
                float4 sv = *(const float4*)&S[r][c];
                float4 se = *(const float4*)&selp[(size_t)r * LSEQ + c];
                int4  mv = *(const int4*)&mp[(size_t)r * LSEQ + c];
                float x0 = sv.x * scale + se.x; if (mv.x == 0) x0 = -1e12f;
                float x1 = sv.y * scale + se.y; if (mv.y == 0) x1 = -1e12f;
                float x2 = sv.z * scale + se.z; if (mv.z == 0) x2 = -1e12f;
                float x3 = sv.w * scale + se.w; if (mv.w == 0) x3 = -1e12f;
                vals[4 * i + 0] = x0; vals[4 * i + 1] = x1;
                vals[4 * i + 2] = x2; vals[4 * i + 3] = x3;
                lmax = fmaxf(lmax, fmaxf(fmaxf(x0, x1), fmaxf(x2, x3)));
            }
            #pragma unroll
            for (int o = 16; o > 0; o >>= 1)
                lmax = fmaxf(lmax, __shfl_xor_sync(0xffffffffu, lmax, o));
            float lsum = 0.f;
            #pragma unroll
            for (int i = 0; i < 16; ++i) {
                vals[i] = __expf(vals[i] - lmax);
                lsum += vals[i];
            }
            #pragma unroll
            for (int o = 16; o > 0; o >>= 1)
                lsum += __shfl_xor_sync(0xffffffffu, lsum, o);
            const float inv = 1.0f / lsum;
            #pragma unroll
            for (int i = 0; i < 4; ++i) {
                const int c = i * 128 + lane * 4;
                float4 a4;
                a4.x = vals[4 * i + 0] * inv;
                a4.y = vals[4 * i + 1] * inv;
                a4.z = vals[4 * i + 2] * inv;
                a4.w = vals[4 * i + 3] * inv;
                *(float4*)&S[r][c] = a4;
                *(float4*)&attnp[(size_t)r * LSEQ + c] = a4;
            }
        }
    }
    __syncthreads();

    // ---- phase 3: ctx = P(S) @ V via tf32 mma, double-buffered V tiles ----
    {
        float acc[2][4];
        #pragma unroll
        for (int nt = 0; nt < 2; ++nt)
            #pragma unroll
            for (int j = 0; j < 4; ++j) acc[nt][j] = 0.f;

        for (int vt = 0; vt < LSEQ / TK; ++vt) {
            CP_WAIT0();
            __syncthreads();
            if (vt + 1 < LSEQ / TK) {
                const float* vn = vg + (size_t)(vt + 1) * TK * DH;
                #pragma unroll
                for (int i = tid; i < TK * DH / 4; i += NTHR) {
                    int e = i * 4, r = e >> 6, c = e & 63;
                    cp_async16(&KV[(vt + 1) & 1][r][c], vn + e);
                }
                CP_COMMIT();
            }

            float (*Vs)[QS_STRIDE] = KV[vt & 1];
            #pragma unroll
            for (int ks = 0; ks < TK / 8; ++ks) {
                const int sk = vt * TK + ks * 8;   // S column (k index)
                const int vk = ks * 8;             // V smem row
                uint32_t a[4];
                a[0] = f2tf(S[wm * 16 + g    ][sk + t    ]);
                a[1] = f2tf(S[wm * 16 + g + 8][sk + t    ]);
                a[2] = f2tf(S[wm * 16 + g    ][sk + t + 4]);
                a[3] = f2tf(S[wm * 16 + g + 8][sk + t + 4]);
                #pragma unroll
                for (int nt = 0; nt < 2; ++nt) {
                    const int n0 = wn * 16 + nt * 8;
                    uint32_t b[2];
                    b[0] = f2tf(Vs[vk + t    ][n0 + g]);
                    b[1] = f2tf(Vs[vk + t + 4][n0 + g]);
                    mma_tf32(acc[nt], a, b);
                }
            }
            __syncthreads();   // buf[vt&1] free for prefetch vt+2
        }

        float* cp = ctx + ((size_t)bh * LSEQ + (size_t)qt * TQ) * DH;
        #pragma unroll
        for (int nt = 0; nt < 2; ++nt) {
            const int n0 = wn * 16 + nt * 8 + 2 * t;
            float2 lo = make_float2(acc[nt][0], acc[nt][1]);
            float2 hi = make_float2(acc[nt][2], acc[nt][3]);
            *(float2*)&cp[(size_t)(wm * 16 + g    ) * DH + n0] = lo;
            *(float2*)&cp[(size_t)(wm * 16 + g + 8) * DH + n0] = hi;
        }
    }
}

extern "C" void kernel_launch(void* const* d_in, const int* in_sizes, int n_in,
                              void* d_out, int out_size)
{
    (void)in_sizes; (void)n_in; (void)out_size;
    const float* q = (const float*)d_in[0];
    const float* k = (const float*)d_in[1];
    const float* v = (const float*)d_in[2];
    const float* sel = (const float*)d_in[3];
    const int* mask = (const int*)d_in[4];

    float* ctx  = (float*)d_out;                          // [128,512,64]
    float* attn = ctx + (size_t)BH * LSEQ * DH;           // [128,512,512]

    cudaFuncSetAttribute(attn_fused_kernel,
                         cudaFuncAttributeMaxDynamicSharedMemorySize, (int)SMEM_BYTES);

    dim3 grid(LSEQ / TQ, BH);   // (8, 128) = 1024 blocks
    attn_fused_kernel<<<grid, NTHR, SMEM_BYTES>>>(q, k, v, sel, mask, ctx, attn);
}